// round 1
// baseline (speedup 1.0000x reference)
#include <cuda_runtime.h>
#include <cstdint>

#define NN 100000
#define NE 1600000
#define D  128
#define NL 3

// Scratch (allocation-free rule: __device__ globals)
__device__ __align__(16) float g_buf0[(size_t)NN * D];
__device__ __align__(16) float g_buf1[(size_t)NN * D];
__device__ __align__(16) float g_agg [(size_t)NN * D];

// ---------------------------------------------------------------------------
// helpers: packed f32x2 math (Blackwell FFMA2 — only reachable via PTX)
// ---------------------------------------------------------------------------
__device__ __forceinline__ unsigned long long pk2(float v) {
    unsigned long long r;
    asm("mov.b64 %0, {%1, %1};" : "=l"(r) : "f"(v));
    return r;
}
__device__ __forceinline__ void upk2(unsigned long long p, float& lo, float& hi) {
    asm("mov.b64 {%0, %1}, %2;" : "=f"(lo), "=f"(hi) : "l"(p));
}
__device__ __forceinline__ void fma2(unsigned long long& d,
                                     unsigned long long a,
                                     unsigned long long b) {
    asm("fma.rn.f32x2 %0, %1, %2, %0;" : "+l"(d) : "l"(a), "l"(b));
}

// ---------------------------------------------------------------------------
// zero kernel (agg init)
// ---------------------------------------------------------------------------
__global__ void zero_kernel(float4* __restrict__ p, int n4) {
    int i = blockIdx.x * blockDim.x + threadIdx.x;
    int stride = gridDim.x * blockDim.x;
    for (; i < n4; i += stride) p[i] = make_float4(0.f, 0.f, 0.f, 0.f);
}

// ---------------------------------------------------------------------------
// scatter: one warp per edge; lane l handles float4 l of the 128-f row.
// red.global.add.v4.f32 -> L2 atomic ALU, 16B granularity.
// ---------------------------------------------------------------------------
__global__ void scatter_kernel(const float* __restrict__ x,
                               const int* __restrict__ src,
                               const int* __restrict__ dst,
                               float* __restrict__ agg) {
    int w = (blockIdx.x * blockDim.x + threadIdx.x) >> 5;
    int lane = threadIdx.x & 31;
    if (w >= NE) return;
    int s = __ldg(src + w);
    int d = __ldg(dst + w);
    const float4* xs = (const float4*)(x + (size_t)s * D);
    float4 v = __ldg(xs + lane);
    float* ap = agg + (size_t)d * D + lane * 4;
    asm volatile("red.global.add.v4.f32 [%0], {%1,%2,%3,%4};"
                 :: "l"(ap), "f"(v.x), "f"(v.y), "f"(v.z), "f"(v.w)
                 : "memory");
}

// ---------------------------------------------------------------------------
// fused MLP: out = [relu]( relu((x+agg) @ W1 + b1) @ W2 + b2 )
// Tile: 128 rows x 128 cols per block, 256 threads, 8x8 outputs/thread,
// f32x2-packed accumulators. W1, W2, A-tile in smem; A-tile reused for H.
// ---------------------------------------------------------------------------
#define TM 128
#define AS_STRIDE 132   // pad: avoid bank conflicts on strided row access

__global__ __launch_bounds__(256, 1)
void mlp_kernel(const float* __restrict__ xin, const float* __restrict__ agg,
                const float* __restrict__ W1, const float* __restrict__ b1,
                const float* __restrict__ W2, const float* __restrict__ b2,
                float* __restrict__ out, int relu_out) {
    extern __shared__ float smem[];
    float* Ws1 = smem;                        // 128*128
    float* Ws2 = Ws1 + D * D;                 // 128*128
    float* As  = Ws2 + D * D;                 // TM * AS_STRIDE
    float* bs1 = As + TM * AS_STRIDE;         // 128
    float* bs2 = bs1 + D;                     // 128

    const int tid = threadIdx.x;

    // cooperative load of weights + biases
    {
        const float4* w1g = (const float4*)W1;
        const float4* w2g = (const float4*)W2;
        float4* w1s = (float4*)Ws1;
        float4* w2s = (float4*)Ws2;
        #pragma unroll
        for (int i = tid; i < D * D / 4; i += 256) {
            w1s[i] = __ldg(w1g + i);
            w2s[i] = __ldg(w2g + i);
        }
        if (tid < D) { bs1[tid] = __ldg(b1 + tid); bs2[tid] = __ldg(b2 + tid); }
    }

    // load A tile = x + agg  (128 rows x 32 float4)
    const int row0 = blockIdx.x * TM;
    for (int i = tid; i < TM * (D / 4); i += 256) {
        int r = i >> 5;
        int c = i & 31;
        int gr = row0 + r;
        float4 v;
        if (gr < NN) {
            const float4* xp = (const float4*)(xin + (size_t)gr * D) + c;
            const float4* ap = (const float4*)(agg + (size_t)gr * D) + c;
            float4 a = __ldg(xp), b = __ldg(ap);
            v = make_float4(a.x + b.x, a.y + b.y, a.z + b.z, a.w + b.w);
        } else {
            v = make_float4(0.f, 0.f, 0.f, 0.f);
        }
        ((float4*)&As[r * AS_STRIDE])[c] = v;
    }
    __syncthreads();

    const int mi = tid >> 4;   // 0..15 -> rows mi*8 .. mi*8+7
    const int ni = tid & 15;   // 0..15 -> cols ni*8 .. ni*8+7

    unsigned long long acc[8][4];

    // GEMM over smem weights Wsm (acc = A_tile @ Wsm)
    auto gemm = [&](const float* __restrict__ Wsm) {
        #pragma unroll
        for (int r = 0; r < 8; r++)
            #pragma unroll
            for (int c = 0; c < 4; c++) acc[r][c] = 0ull;

        const float* abase = As + (mi * 8) * AS_STRIDE;
        #pragma unroll 2
        for (int k = 0; k < D; k += 2) {
            // W rows k and k+1, 8 consecutive cols -> 4 packed pairs each
            ulonglong2 wA0 = *(const ulonglong2*)&Wsm[k * D + ni * 8];
            ulonglong2 wA1 = *(const ulonglong2*)&Wsm[k * D + ni * 8 + 4];
            ulonglong2 wB0 = *(const ulonglong2*)&Wsm[(k + 1) * D + ni * 8];
            ulonglong2 wB1 = *(const ulonglong2*)&Wsm[(k + 1) * D + ni * 8 + 4];
            unsigned long long wk0[4] = {wA0.x, wA0.y, wA1.x, wA1.y};
            unsigned long long wk1[4] = {wB0.x, wB0.y, wB1.x, wB1.y};
            #pragma unroll
            for (int r = 0; r < 8; r++) {
                float2 a = *(const float2*)&abase[r * AS_STRIDE + k]; // broadcast (half-warp same addr)
                unsigned long long a0 = pk2(a.x);
                unsigned long long a1 = pk2(a.y);
                #pragma unroll
                for (int c = 0; c < 4; c++) {
                    fma2(acc[r][c], a0, wk0[c]);
                    fma2(acc[r][c], a1, wk1[c]);
                }
            }
        }
    };

    // ---- GEMM1: H = relu(A @ W1 + b1) ----
    gemm(Ws1);
    __syncthreads();   // everyone done reading As before we overwrite it with H

    #pragma unroll
    for (int r = 0; r < 8; r++) {
        float* drow = &As[(mi * 8 + r) * AS_STRIDE + ni * 8];
        #pragma unroll
        for (int c = 0; c < 4; c++) {
            float lo, hi;
            upk2(acc[r][c], lo, hi);
            int col = ni * 8 + 2 * c;
            lo = fmaxf(lo + bs1[col], 0.f);
            hi = fmaxf(hi + bs1[col + 1], 0.f);
            ((float2*)drow)[c] = make_float2(lo, hi);
        }
    }
    __syncthreads();

    // ---- GEMM2: out = [relu](H @ W2 + b2) ----
    gemm(Ws2);

    #pragma unroll
    for (int r = 0; r < 8; r++) {
        int gr = row0 + mi * 8 + r;
        if (gr >= NN) continue;
        float* orow = out + (size_t)gr * D + ni * 8;
        #pragma unroll
        for (int c = 0; c < 4; c++) {
            float lo, hi;
            upk2(acc[r][c], lo, hi);
            int col = ni * 8 + 2 * c;
            lo += bs2[col];
            hi += bs2[col + 1];
            if (relu_out) { lo = fmaxf(lo, 0.f); hi = fmaxf(hi, 0.f); }
            ((float2*)orow)[c] = make_float2(lo, hi);
        }
    }
}

// ---------------------------------------------------------------------------
// launch
// ---------------------------------------------------------------------------
extern "C" void kernel_launch(void* const* d_in, const int* in_sizes, int n_in,
                              void* d_out, int out_size) {
    const float* x  = (const float*)d_in[0];
    const int*   ei = (const int*)d_in[1];
    const float* W1 = (const float*)d_in[2];
    const float* b1 = (const float*)d_in[3];
    const float* W2 = (const float*)d_in[4];
    const float* b2 = (const float*)d_in[5];
    float* out = (float*)d_out;

    const int* src = ei;
    const int* dst = ei + NE;

    float *p_buf0, *p_buf1, *p_agg;
    cudaGetSymbolAddress((void**)&p_buf0, g_buf0);
    cudaGetSymbolAddress((void**)&p_buf1, g_buf1);
    cudaGetSymbolAddress((void**)&p_agg,  g_agg);

    const size_t smem_bytes = (size_t)(2 * D * D + TM * AS_STRIDE + 2 * D) * sizeof(float);
    cudaFuncSetAttribute(mlp_kernel, cudaFuncAttributeMaxDynamicSharedMemorySize,
                         (int)smem_bytes);

    const int n4 = NN * D / 4;
    const int scat_blocks = (NE * 32 + 255) / 256;
    const int mlp_blocks = (NN + TM - 1) / TM;

    const float* lin[3]  = {x, p_buf0, p_buf1};
    float*       lout[3] = {p_buf0, p_buf1, out};

    for (int l = 0; l < NL; l++) {
        zero_kernel<<<1024, 256>>>((float4*)p_agg, n4);
        scatter_kernel<<<scat_blocks, 256>>>(lin[l], src, dst, p_agg);
        mlp_kernel<<<mlp_blocks, 256, smem_bytes>>>(
            lin[l], p_agg,
            W1 + (size_t)l * D * D, b1 + (size_t)l * D,
            W2 + (size_t)l * D * D, b2 + (size_t)l * D,
            lout[l], (l < NL - 1) ? 1 : 0);
    }
    (void)in_sizes; (void)n_in; (void)out_size;
}